// round 1
// baseline (speedup 1.0000x reference)
#include <cuda_runtime.h>
#include <math.h>

// Problem constants
#define BB   2
#define SS   2048
#define DD   768
#define HH   12
#define HDIM 64
#define HALFW 64
#define NEGV -1000000000.0f

// Scratch (no cudaMalloc allowed)
__device__ float g_qkv[BB * SS * 3 * DD];   // (b, s, [q|k|v] h d)  row = 2304
__device__ float g_att[BB * SS * DD];       // (b, s, h*64+d)

// ---------------------------------------------------------------------------
// SGEMM: C[M,N] = A[M,K] @ B[K,N], all row-major fp32.
// 128x128 block tile, BK=8, 256 threads, 8x8 per-thread micro-tile.
// M % 128 == 0, N % 128 == 0, K % 8 == 0 (true for all three uses).
// ---------------------------------------------------------------------------
__global__ __launch_bounds__(256) void sgemm_kernel(
    const float* __restrict__ A, const float* __restrict__ B,
    float* __restrict__ C, int M, int N, int K)
{
    __shared__ float As[8][132];   // transposed A tile, padded vs bank conflicts
    __shared__ float Bs[8][128];

    const int tid = threadIdx.x;
    const int bm = blockIdx.y * 128;
    const int bn = blockIdx.x * 128;

    const int tx = tid & 15;       // n-direction
    const int ty = tid >> 4;       // m-direction

    // global load indices
    const int arow  = tid >> 1;          // 0..127
    const int acol4 = (tid & 1) * 4;     // 0 or 4
    const int brow  = tid >> 5;          // 0..7
    const int bcol4 = (tid & 31) * 4;    // 0..124

    const float* Aptr = A + (size_t)(bm + arow) * K + acol4;
    const float* Bptr = B + (size_t)brow * N + bn + bcol4;

    float acc[8][8];
    #pragma unroll
    for (int i = 0; i < 8; i++)
        #pragma unroll
        for (int j = 0; j < 8; j++) acc[i][j] = 0.f;

    for (int k0 = 0; k0 < K; k0 += 8) {
        float4 a  = *(const float4*)(Aptr + k0);
        float4 bv = *(const float4*)(Bptr + (size_t)k0 * N);

        As[acol4 + 0][arow] = a.x;
        As[acol4 + 1][arow] = a.y;
        As[acol4 + 2][arow] = a.z;
        As[acol4 + 3][arow] = a.w;
        *(float4*)&Bs[brow][bcol4] = bv;
        __syncthreads();

        #pragma unroll
        for (int kk = 0; kk < 8; kk++) {
            float af[8], bf[8];
            const float4* ap = (const float4*)&As[kk][ty * 8];
            const float4* bp = (const float4*)&Bs[kk][tx * 8];
            float4 a0 = ap[0], a1 = ap[1];
            float4 b0 = bp[0], b1 = bp[1];
            af[0]=a0.x; af[1]=a0.y; af[2]=a0.z; af[3]=a0.w;
            af[4]=a1.x; af[5]=a1.y; af[6]=a1.z; af[7]=a1.w;
            bf[0]=b0.x; bf[1]=b0.y; bf[2]=b0.z; bf[3]=b0.w;
            bf[4]=b1.x; bf[5]=b1.y; bf[6]=b1.z; bf[7]=b1.w;
            #pragma unroll
            for (int i = 0; i < 8; i++)
                #pragma unroll
                for (int j = 0; j < 8; j++)
                    acc[i][j] = fmaf(af[i], bf[j], acc[i][j]);
        }
        __syncthreads();
    }

    #pragma unroll
    for (int i = 0; i < 8; i++) {
        const size_t row = (size_t)(bm + ty * 8 + i) * N + bn + tx * 8;
        float4 c0, c1;
        c0.x = acc[i][0]; c0.y = acc[i][1]; c0.z = acc[i][2]; c0.w = acc[i][3];
        c1.x = acc[i][4]; c1.y = acc[i][5]; c1.z = acc[i][6]; c1.w = acc[i][7];
        *(float4*)&C[row]     = c0;
        *(float4*)&C[row + 4] = c1;
    }
}

// ---------------------------------------------------------------------------
// Sliding-window attention.
// One block per (b, h, 32-query chunk). Keys in [q0-64, q0+31+64] -> <=160.
// Phase mapping (8 warps, 256 threads):
//   scores: warp w owns queries 4w..4w+3, lane owns keys lane*5..lane*5+4
//   softmax: warp w reduces its own 4 rows (stride-32 lanes)
//   output: warp w owns queries 4w..4w+3, lane owns dims 2*lane, 2*lane+1
// Row ownership is warp-private, so only __syncwarp between phases after the
// single block-level __syncthreads following the smem loads.
// ---------------------------------------------------------------------------
__global__ __launch_bounds__(256) void attn_kernel(
    const float* __restrict__ qkv, const float* __restrict__ pmask,
    float* __restrict__ out)
{
    constexpr int QC = 32, KMAX = 160, KPAD = 161;
    extern __shared__ float sm[];
    float* Qs = sm;                     // [QC][HDIM]           2048
    float* Ks = Qs + QC * HDIM;         // [HDIM][KPAD] transp. 10304
    float* Vs = Ks + HDIM * KPAD;       // [KMAX][HDIM]         10240
    float* Ss = Vs + KMAX * HDIM;       // [QC][KMAX]           5120
    float* Pn = Ss + QC * KMAX;         // [KMAX] padding-neg   160

    const int chunk = blockIdx.x, h = blockIdx.y, b = blockIdx.z;
    const int qbase = chunk * QC;
    const int k0   = max(0, qbase - HALFW);
    const int kend = min(SS, qbase + QC + HALFW);
    const int kN   = kend - k0;
    const int tid  = threadIdx.x;

    // Load Q tile
    for (int idx = tid; idx < QC * HDIM; idx += 256) {
        int q = idx >> 6, d = idx & 63;
        Qs[q * HDIM + d] = qkv[((size_t)(b * SS + qbase + q)) * (3 * DD) + h * HDIM + d];
    }
    // Load K (transposed) and V tiles
    for (int idx = tid; idx < kN * HDIM; idx += 256) {
        int k = idx >> 6, d = idx & 63;
        size_t base = ((size_t)(b * SS + k0 + k)) * (3 * DD) + h * HDIM + d;
        Ks[d * KPAD + k] = qkv[base + DD];
        Vs[k * HDIM + d] = qkv[base + 2 * DD];
    }
    for (int k = tid; k < kN; k += 256)
        Pn[k] = (1.0f - pmask[b * SS + k0 + k]) * NEGV;
    __syncthreads();

    const int warp = tid >> 5, lane = tid & 31;
    const int qrow = warp * 4;

    // ---- scores: 4q x 5k micro-tile per thread ----
    float acc[4][5];
    #pragma unroll
    for (int i = 0; i < 4; i++)
        #pragma unroll
        for (int j = 0; j < 5; j++) acc[i][j] = 0.f;

    #pragma unroll 4
    for (int d = 0; d < HDIM; d++) {
        float aq[4];
        #pragma unroll
        for (int i = 0; i < 4; i++) aq[i] = Qs[(qrow + i) * HDIM + d];
        float kv[5];
        #pragma unroll
        for (int j = 0; j < 5; j++) kv[j] = Ks[d * KPAD + lane * 5 + j];
        #pragma unroll
        for (int i = 0; i < 4; i++)
            #pragma unroll
            for (int j = 0; j < 5; j++)
                acc[i][j] = fmaf(aq[i], kv[j], acc[i][j]);
    }

    const float scale = 0.125f;   // 1/sqrt(64)
    #pragma unroll
    for (int i = 0; i < 4; i++) {
        int gq = qbase + qrow + i;
        #pragma unroll
        for (int j = 0; j < 5; j++) {
            int k = lane * 5 + j;
            if (k < kN) {
                int gk = k0 + k;
                int dd = gq - gk; if (dd < 0) dd = -dd;
                float s = (dd <= HALFW) ? (acc[i][j] * scale + Pn[k]) : -1e30f;
                Ss[(qrow + i) * KMAX + k] = s;
            }
        }
    }
    __syncwarp();

    // ---- softmax over each of this warp's 4 rows ----
    #pragma unroll
    for (int i = 0; i < 4; i++) {
        float* row = &Ss[(qrow + i) * KMAX];
        float m = -1e30f;
        for (int k = lane; k < kN; k += 32) m = fmaxf(m, row[k]);
        #pragma unroll
        for (int o = 16; o; o >>= 1) m = fmaxf(m, __shfl_xor_sync(0xffffffffu, m, o));
        float sum = 0.f;
        for (int k = lane; k < kN; k += 32) {
            float e = __expf(row[k] - m);
            row[k] = e;
            sum += e;
        }
        #pragma unroll
        for (int o = 16; o; o >>= 1) sum += __shfl_xor_sync(0xffffffffu, sum, o);
        float inv = 1.f / sum;
        for (int k = lane; k < kN; k += 32) row[k] *= inv;
    }
    __syncwarp();

    // ---- output: 4q x 2d micro-tile per thread ----
    float o[4][2];
    #pragma unroll
    for (int i = 0; i < 4; i++) { o[i][0] = 0.f; o[i][1] = 0.f; }
    const int d0 = lane * 2;
    for (int k = 0; k < kN; k++) {
        float2 v = *(const float2*)&Vs[k * HDIM + d0];
        #pragma unroll
        for (int i = 0; i < 4; i++) {
            float p = Ss[(qrow + i) * KMAX + k];
            o[i][0] = fmaf(p, v.x, o[i][0]);
            o[i][1] = fmaf(p, v.y, o[i][1]);
        }
    }
    #pragma unroll
    for (int i = 0; i < 4; i++) {
        int gq = qbase + qrow + i;
        float2 r; r.x = o[i][0]; r.y = o[i][1];
        *(float2*)&out[((size_t)(b * SS + gq)) * DD + h * HDIM + d0] = r;
    }
}

// ---------------------------------------------------------------------------
extern "C" void kernel_launch(void* const* d_in, const int* in_sizes, int n_in,
                              void* d_out, int out_size)
{
    const float* x    = (const float*)d_in[0];
    const float* pm   = (const float*)d_in[1];
    const float* Wqkv = (const float*)d_in[2];
    const float* Wo   = (const float*)d_in[3];
    float* out = (float*)d_out;

    float *qkv_ptr, *att_ptr;
    cudaGetSymbolAddress((void**)&qkv_ptr, g_qkv);
    cudaGetSymbolAddress((void**)&att_ptr, g_att);

    const int M = BB * SS;  // 4096

    // 1) QKV projection: (4096 x 768) @ (768 x 2304)
    sgemm_kernel<<<dim3(3 * DD / 128, M / 128), 256>>>(x, Wqkv, qkv_ptr, M, 3 * DD, DD);

    // 2) Sliding-window attention
    const int smem_bytes = (32 * HDIM + HDIM * 161 + 160 * HDIM + 32 * 160 + 160) * (int)sizeof(float);
    cudaFuncSetAttribute(attn_kernel, cudaFuncAttributeMaxDynamicSharedMemorySize, smem_bytes);
    attn_kernel<<<dim3(SS / 32, HH, BB), 256, smem_bytes>>>(qkv_ptr, pm, att_ptr);

    // 3) Output projection: (4096 x 768) @ (768 x 768)
    sgemm_kernel<<<dim3(DD / 128, M / 128), 256>>>(att_ptr, Wo, out, M, DD, DD);
}

// round 3
// speedup vs baseline: 1.6705x; 1.6705x over previous
#include <cuda_runtime.h>
#include <cuda_bf16.h>
#include <cstdint>
#include <math.h>

// Problem constants
#define BB   2
#define SS   2048
#define DD   768
#define HH   12
#define HDIM 64
#define HALFW 64
#define NEGV -1000000000.0f

// ---------------------------------------------------------------------------
// Scratch (no cudaMalloc allowed)
// ---------------------------------------------------------------------------
__device__ float g_qkv[BB * SS * 3 * DD];            // fp32 qkv  (4096 x 2304)
__device__ float g_att[BB * SS * DD];                // fp32 attn out (4096 x 768)
__device__ __nv_bfloat16 g_xhi[BB * SS * DD];        // x split
__device__ __nv_bfloat16 g_xlo[BB * SS * DD];
__device__ __nv_bfloat16 g_wqh[3 * DD * DD];         // Wqkv^T split (2304 x 768)
__device__ __nv_bfloat16 g_wql[3 * DD * DD];
__device__ __nv_bfloat16 g_woh[DD * DD];             // Wo^T split (768 x 768)
__device__ __nv_bfloat16 g_wol[DD * DD];
__device__ __nv_bfloat16 g_ahi[BB * SS * DD];        // att split
__device__ __nv_bfloat16 g_alo[BB * SS * DD];

// ---------------------------------------------------------------------------
// Split / transpose-split conversion kernels
// ---------------------------------------------------------------------------
__global__ __launch_bounds__(256) void split_kernel(
    const float* __restrict__ in, __nv_bfloat16* __restrict__ hi,
    __nv_bfloat16* __restrict__ lo, int n)
{
    int i = blockIdx.x * 256 + threadIdx.x;
    if (i < n) {
        float v = in[i];
        __nv_bfloat16 h = __float2bfloat16(v);
        hi[i] = h;
        lo[i] = __float2bfloat16(v - __bfloat162float(h));
    }
}

// in[K x N] -> hiT/loT [N x K]
__global__ __launch_bounds__(256) void splitT_kernel(
    const float* __restrict__ in, __nv_bfloat16* __restrict__ hiT,
    __nv_bfloat16* __restrict__ loT, int K, int N)
{
    __shared__ float t[32][33];
    const int k0 = blockIdx.y * 32, n0 = blockIdx.x * 32;
    const int tx = threadIdx.x, ty = threadIdx.y;   // 32 x 8
    #pragma unroll
    for (int i = 0; i < 32; i += 8)
        t[ty + i][tx] = in[(size_t)(k0 + ty + i) * N + n0 + tx];
    __syncthreads();
    #pragma unroll
    for (int i = 0; i < 32; i += 8) {
        float v = t[tx][ty + i];
        __nv_bfloat16 h = __float2bfloat16(v);
        size_t o = (size_t)(n0 + ty + i) * K + k0 + tx;
        hiT[o] = h;
        loT[o] = __float2bfloat16(v - __bfloat162float(h));
    }
}

// ---------------------------------------------------------------------------
// bf16x3 mma.sync GEMM: C[M,N] = A[M,K] @ Bt[N,K]^T, fp32 accumulate.
// Block tile 128x128x32, 8 warps (2m x 4n), warp tile 64x32 via m16n8k16.
// M%128==0, N%128==0, K%32==0.
// ---------------------------------------------------------------------------
#define SMS 40   // smem row stride in bf16 elems (32 + 8 pad)

__device__ __forceinline__ void mma16816(float* c, const uint32_t* a, const uint32_t* b)
{
    asm volatile(
        "mma.sync.aligned.m16n8k16.row.col.f32.bf16.bf16.f32 "
        "{%0,%1,%2,%3}, {%4,%5,%6,%7}, {%8,%9}, {%0,%1,%2,%3};"
        : "+f"(c[0]), "+f"(c[1]), "+f"(c[2]), "+f"(c[3])
        : "r"(a[0]), "r"(a[1]), "r"(a[2]), "r"(a[3]), "r"(b[0]), "r"(b[1]));
}

__global__ __launch_bounds__(256, 2) void gemm_bf16x3_kernel(
    const __nv_bfloat16* __restrict__ Ahi, const __nv_bfloat16* __restrict__ Alo,
    const __nv_bfloat16* __restrict__ Bthi, const __nv_bfloat16* __restrict__ Btlo,
    float* __restrict__ C, int M, int N, int K)
{
    __shared__ __nv_bfloat16 smb[4][128 * SMS];   // Ah, Al, Bh, Bl

    const int tid = threadIdx.x;
    const int wid = tid >> 5, lane = tid & 31;
    const int g = lane >> 2, tg = lane & 3;
    const int wm = wid >> 2, wn = wid & 3;        // 2 x 4 warp grid
    const int mbase = wm * 64, nbase = wn * 32;
    const int bm = blockIdx.y * 128, bn = blockIdx.x * 128;

    const __nv_bfloat16* srcs[4] = {
        Ahi + (size_t)bm * K, Alo + (size_t)bm * K,
        Bthi + (size_t)bn * K, Btlo + (size_t)bn * K };

    float acc[4][4][4];
    #pragma unroll
    for (int i = 0; i < 4; i++)
        #pragma unroll
        for (int j = 0; j < 4; j++)
            #pragma unroll
            for (int c = 0; c < 4; c++) acc[i][j][c] = 0.f;

    // per-thread global/smem load coords: 512 uint4 per tile, 2 per thread
    const int lr0 = tid >> 2, lq = tid & 3;       // rows 0..63 / 64..127

    for (int k0 = 0; k0 < K; k0 += 32) {
        #pragma unroll
        for (int t = 0; t < 4; t++) {
            const __nv_bfloat16* s = srcs[t] + k0 + lq * 8;
            uint4 v0 = *(const uint4*)(s + (size_t)lr0 * K);
            uint4 v1 = *(const uint4*)(s + (size_t)(lr0 + 64) * K);
            *(uint4*)&smb[t][lr0 * SMS + lq * 8] = v0;
            *(uint4*)&smb[t][(lr0 + 64) * SMS + lq * 8] = v1;
        }
        __syncthreads();

        // 3 passes: (Ah,Bh), (Ah,Bl), (Al,Bh)
        #pragma unroll
        for (int pass = 0; pass < 3; pass++) {
            const int sa = (pass == 2) ? 1 : 0;
            const int sb = (pass == 1) ? 3 : 2;
            #pragma unroll
            for (int kk = 0; kk < 32; kk += 16) {
                uint32_t af[4][4], bfr[4][2];
                #pragma unroll
                for (int mt = 0; mt < 4; mt++) {
                    const __nv_bfloat16* ap = &smb[sa][(mbase + mt * 16 + g) * SMS + kk + tg * 2];
                    af[mt][0] = *(const uint32_t*)(ap);
                    af[mt][1] = *(const uint32_t*)(ap + 8 * SMS);
                    af[mt][2] = *(const uint32_t*)(ap + 8);
                    af[mt][3] = *(const uint32_t*)(ap + 8 * SMS + 8);
                }
                #pragma unroll
                for (int nt = 0; nt < 4; nt++) {
                    const __nv_bfloat16* bp = &smb[sb][(nbase + nt * 8 + g) * SMS + kk + tg * 2];
                    bfr[nt][0] = *(const uint32_t*)(bp);
                    bfr[nt][1] = *(const uint32_t*)(bp + 8);
                }
                #pragma unroll
                for (int mt = 0; mt < 4; mt++)
                    #pragma unroll
                    for (int nt = 0; nt < 4; nt++)
                        mma16816(acc[mt][nt], af[mt], bfr[nt]);
            }
        }
        __syncthreads();
    }

    // Epilogue: direct fp32 stores (float2 per fragment half)
    #pragma unroll
    for (int mt = 0; mt < 4; mt++) {
        #pragma unroll
        for (int nt = 0; nt < 4; nt++) {
            const int row = bm + mbase + mt * 16 + g;
            const int col = bn + nbase + nt * 8 + tg * 2;
            float2 v0; v0.x = acc[mt][nt][0]; v0.y = acc[mt][nt][1];
            float2 v1; v1.x = acc[mt][nt][2]; v1.y = acc[mt][nt][3];
            *(float2*)&C[(size_t)row * N + col] = v0;
            *(float2*)&C[(size_t)(row + 8) * N + col] = v1;
        }
    }
}

// ---------------------------------------------------------------------------
// Sliding-window attention (unchanged from round 1)
// ---------------------------------------------------------------------------
__global__ __launch_bounds__(256) void attn_kernel(
    const float* __restrict__ qkv, const float* __restrict__ pmask,
    float* __restrict__ out)
{
    constexpr int QC = 32, KMAX = 160, KPAD = 161;
    extern __shared__ float sm[];
    float* Qs = sm;
    float* Ks = Qs + QC * HDIM;
    float* Vs = Ks + HDIM * KPAD;
    float* Ss = Vs + KMAX * HDIM;
    float* Pn = Ss + QC * KMAX;

    const int chunk = blockIdx.x, h = blockIdx.y, b = blockIdx.z;
    const int qbase = chunk * QC;
    const int k0   = max(0, qbase - HALFW);
    const int kend = min(SS, qbase + QC + HALFW);
    const int kN   = kend - k0;
    const int tid  = threadIdx.x;

    for (int idx = tid; idx < QC * HDIM; idx += 256) {
        int q = idx >> 6, d = idx & 63;
        Qs[q * HDIM + d] = qkv[((size_t)(b * SS + qbase + q)) * (3 * DD) + h * HDIM + d];
    }
    for (int idx = tid; idx < kN * HDIM; idx += 256) {
        int k = idx >> 6, d = idx & 63;
        size_t base = ((size_t)(b * SS + k0 + k)) * (3 * DD) + h * HDIM + d;
        Ks[d * KPAD + k] = qkv[base + DD];
        Vs[k * HDIM + d] = qkv[base + 2 * DD];
    }
    for (int k = tid; k < kN; k += 256)
        Pn[k] = (1.0f - pmask[b * SS + k0 + k]) * NEGV;
    __syncthreads();

    const int warp = tid >> 5, lane = tid & 31;
    const int qrow = warp * 4;

    float acc[4][5];
    #pragma unroll
    for (int i = 0; i < 4; i++)
        #pragma unroll
        for (int j = 0; j < 5; j++) acc[i][j] = 0.f;

    #pragma unroll 4
    for (int d = 0; d < HDIM; d++) {
        float aq[4];
        #pragma unroll
        for (int i = 0; i < 4; i++) aq[i] = Qs[(qrow + i) * HDIM + d];
        float kv[5];
        #pragma unroll
        for (int j = 0; j < 5; j++) kv[j] = Ks[d * KPAD + lane * 5 + j];
        #pragma unroll
        for (int i = 0; i < 4; i++)
            #pragma unroll
            for (int j = 0; j < 5; j++)
                acc[i][j] = fmaf(aq[i], kv[j], acc[i][j]);
    }

    const float scale = 0.125f;
    #pragma unroll
    for (int i = 0; i < 4; i++) {
        int gq = qbase + qrow + i;
        #pragma unroll
        for (int j = 0; j < 5; j++) {
            int k = lane * 5 + j;
            if (k < kN) {
                int gk = k0 + k;
                int dd = gq - gk; if (dd < 0) dd = -dd;
                float s = (dd <= HALFW) ? (acc[i][j] * scale + Pn[k]) : -1e30f;
                Ss[(qrow + i) * KMAX + k] = s;
            }
        }
    }
    __syncwarp();

    #pragma unroll
    for (int i = 0; i < 4; i++) {
        float* row = &Ss[(qrow + i) * KMAX];
        float m = -1e30f;
        for (int k = lane; k < kN; k += 32) m = fmaxf(m, row[k]);
        #pragma unroll
        for (int o = 16; o; o >>= 1) m = fmaxf(m, __shfl_xor_sync(0xffffffffu, m, o));
        float sum = 0.f;
        for (int k = lane; k < kN; k += 32) {
            float e = __expf(row[k] - m);
            row[k] = e;
            sum += e;
        }
        #pragma unroll
        for (int o = 16; o; o >>= 1) sum += __shfl_xor_sync(0xffffffffu, sum, o);
        float inv = 1.f / sum;
        for (int k = lane; k < kN; k += 32) row[k] *= inv;
    }
    __syncwarp();

    float o[4][2];
    #pragma unroll
    for (int i = 0; i < 4; i++) { o[i][0] = 0.f; o[i][1] = 0.f; }
    const int d0 = lane * 2;
    for (int k = 0; k < kN; k++) {
        float2 v = *(const float2*)&Vs[k * HDIM + d0];
        #pragma unroll
        for (int i = 0; i < 4; i++) {
            float p = Ss[(qrow + i) * KMAX + k];
            o[i][0] = fmaf(p, v.x, o[i][0]);
            o[i][1] = fmaf(p, v.y, o[i][1]);
        }
    }
    #pragma unroll
    for (int i = 0; i < 4; i++) {
        int gq = qbase + qrow + i;
        float2 r; r.x = o[i][0]; r.y = o[i][1];
        *(float2*)&out[((size_t)(b * SS + gq)) * DD + h * HDIM + d0] = r;
    }
}

// ---------------------------------------------------------------------------
extern "C" void kernel_launch(void* const* d_in, const int* in_sizes, int n_in,
                              void* d_out, int out_size)
{
    const float* x    = (const float*)d_in[0];
    const float* pm   = (const float*)d_in[1];
    const float* Wqkv = (const float*)d_in[2];
    const float* Wo   = (const float*)d_in[3];
    float* out = (float*)d_out;

    float *qkv_p, *att_p;
    __nv_bfloat16 *xhi, *xlo, *wqh, *wql, *woh, *wol, *ahi, *alo;
    cudaGetSymbolAddress((void**)&qkv_p, g_qkv);
    cudaGetSymbolAddress((void**)&att_p, g_att);
    cudaGetSymbolAddress((void**)&xhi, g_xhi);
    cudaGetSymbolAddress((void**)&xlo, g_xlo);
    cudaGetSymbolAddress((void**)&wqh, g_wqh);
    cudaGetSymbolAddress((void**)&wql, g_wql);
    cudaGetSymbolAddress((void**)&woh, g_woh);
    cudaGetSymbolAddress((void**)&wol, g_wol);
    cudaGetSymbolAddress((void**)&ahi, g_ahi);
    cudaGetSymbolAddress((void**)&alo, g_alo);

    const int M = BB * SS;            // 4096
    const int nx = M * DD;            // 3.1M

    const int attn_smem = (32 * HDIM + HDIM * 161 + 160 * HDIM + 32 * 160 + 160) * (int)sizeof(float);
    static bool attr_done = false;
    if (!attr_done) {
        cudaFuncSetAttribute(attn_kernel,
                             cudaFuncAttributeMaxDynamicSharedMemorySize, attn_smem);
        attr_done = true;
    }

    // Input conversions
    split_kernel<<<(nx + 255) / 256, 256>>>(x, xhi, xlo, nx);
    splitT_kernel<<<dim3(3 * DD / 32, DD / 32), dim3(32, 8)>>>(Wqkv, wqh, wql, DD, 3 * DD);
    splitT_kernel<<<dim3(DD / 32, DD / 32), dim3(32, 8)>>>(Wo, woh, wol, DD, DD);

    // 1) QKV projection on tensor cores: (4096 x 768) @ (768 x 2304)
    gemm_bf16x3_kernel<<<dim3(3 * DD / 128, M / 128), 256>>>(
        xhi, xlo, wqh, wql, qkv_p, M, 3 * DD, DD);

    // 2) Sliding-window attention
    attn_kernel<<<dim3(SS / 32, HH, BB), 256, attn_smem>>>(qkv_p, pm, att_p);

    // 3) Output projection on tensor cores: (4096 x 768) @ (768 x 768)
    split_kernel<<<(nx + 255) / 256, 256>>>(att_p, ahi, alo, nx);
    gemm_bf16x3_kernel<<<dim3(DD / 128, M / 128), 256>>>(
        ahi, alo, woh, wol, out, M, DD, DD);
}